// round 7
// baseline (speedup 1.0000x reference)
#include <cuda_runtime.h>
#include <cstdint>
#include <cstddef>

namespace {
constexpr int kM = 64;
constexpr int kK = 4096;
constexpr int kN = 14336;
constexpr int kBN = 16;                 // unit tile width
constexpr int kBK = 128;                // one quant group per chunk
constexpr int kHalfK = kK / 2;          // 2048
constexpr int kChunks = kHalfK / kBK;   // 16 chunks per unit
constexpr int kTilesN = kN / kBN;       // 896
constexpr int kUnits = kTilesN * 2;     // x2 K-halves
constexpr int kAStride = 2064;          // 2048 + 16 pad -> conflict-free LDSM
constexpr int kASmem = kM * kAStride;   // 132096 B
constexpr int kThreads = 256;
}

// device-global scratch (no allocations allowed)
__device__ __align__(16) int8_t g_x8[kM * kK];       // packed int8 activations
__device__ __align__(16) int g_part[2][kM * kN];     // per-K-half int32 partials
__device__ int g_counter;                            // work-stealing cursor

__global__ void pack_x_kernel(const int* __restrict__ x, int gemm_grid) {
    if (blockIdx.x == 0 && threadIdx.x == 0) g_counter = gemm_grid;
    int tid = blockIdx.x * blockDim.x + threadIdx.x;  // 16384 threads
#pragma unroll
    for (int j = 0; j < 4; ++j) {
        int idx = tid + 16384 * j;                    // int4 index over M*K/4
        int4 v = __ldg(((const int4*)x) + idx);
        uint32_t w = (uint32_t)(v.x & 0xff) | ((uint32_t)(v.y & 0xff) << 8)
                   | ((uint32_t)(v.z & 0xff) << 16) | ((uint32_t)(v.w & 0xff) << 24);
        ((uint32_t*)g_x8)[idx] = w;
    }
}

// ---------------- PTX helpers ----------------
__device__ __forceinline__ uint32_t smem_u32(const void* p) {
    return (uint32_t)__cvta_generic_to_shared(p);
}
__device__ __forceinline__ void cp_async16(uint32_t dst, const void* src) {
    asm volatile("cp.async.ca.shared.global [%0], [%1], 16;\n" :: "r"(dst), "l"(src));
}
__device__ __forceinline__ void cp_commit() { asm volatile("cp.async.commit_group;\n"); }
__device__ __forceinline__ void cp_wait_all() { asm volatile("cp.async.wait_group 0;\n" ::: "memory"); }
__device__ __forceinline__ uint32_t prmt(uint32_t a, uint32_t b, uint32_t sel) {
    uint32_t d;
    asm("prmt.b32 %0, %1, %2, %3;" : "=r"(d) : "r"(a), "r"(b), "r"(sel));
    return d;
}
__device__ __forceinline__ void ldmatrix_x4(uint32_t r[4], uint32_t addr) {
    asm volatile("ldmatrix.sync.aligned.m8n8.x4.shared.b16 {%0,%1,%2,%3}, [%4];"
                 : "=r"(r[0]), "=r"(r[1]), "=r"(r[2]), "=r"(r[3]) : "r"(addr));
}
__device__ __forceinline__ void mma_s8(int c[4], uint32_t a0, uint32_t a1, uint32_t a2,
                                       uint32_t a3, uint32_t b0, uint32_t b1) {
    asm volatile(
        "mma.sync.aligned.m16n8k32.row.col.s32.s8.s8.s32 "
        "{%0,%1,%2,%3}, {%4,%5,%6,%7}, {%8,%9}, {%0,%1,%2,%3};\n"
        : "+r"(c[0]), "+r"(c[1]), "+r"(c[2]), "+r"(c[3])
        : "r"(a0), "r"(a1), "r"(a2), "r"(a3), "r"(b0), "r"(b1));
}

// ---------------- persistent barrier-free GEMM ----------------
__global__ void __launch_bounds__(kThreads, 1)
w4a8_gemm(const int* __restrict__ qweight,
          const int* __restrict__ s2_scales,
          const int* __restrict__ s2_zeros) {
    extern __shared__ __align__(16) int8_t As[];     // [64][kAStride] persistent A half
    __shared__ int s_next[2];                        // next-unit broadcast (dbl-buffered)

    const int tid = threadIdx.x;
    const int warp = tid >> 5;
    const int lane = tid & 31;
    const int mt = warp & 3;        // 16-row m-tile
    const int nt = warp >> 2;       // 8-col strip (0..1)
    const int lq = lane & 3;        // k-quarter within 16-k group
    const int lcol = lane >> 2;     // B fragment column 0..7
    const uint32_t As_u = smem_u32(As);
    const uint32_t a_off = (uint32_t)((mt * 16 + (lane & 7) + ((lane >> 3) & 1) * 8) * kAStride
                                      + ((lane >> 4) & 1) * 16);

    int u = blockIdx.x;
    int cur_half = -1;
    int u_par = 0;
    int u_next = 0;

    int4 qv[2][8];
    int s2s[2], zzs[2];

    // load B-fragment source data for (unit, chunk) into register slot
    auto ldg_q = [&](int unit, int c, int slot) {
        const int h = unit >= kTilesN ? 1 : 0;
        const int tile = unit - h * kTilesN;
        const int n = tile * kBN + nt * 8 + lcol;
        const int4* qr = (const int4*)qweight + (size_t)n * (kK / 4) + h * (kHalfK / 4);
#pragma unroll
        for (int ks = 0; ks < 4; ++ks) {
            qv[slot][ks * 2]     = __ldcs(qr + c * 32 + ks * 8 + lq);
            qv[slot][ks * 2 + 1] = __ldcs(qr + c * 32 + ks * 8 + 4 + lq);
        }
        const int g = h * kChunks + c;
        s2s[slot] = __ldg(s2_scales + (size_t)g * kN + n);
        zzs[slot] = __ldg(s2_zeros + (size_t)g * kN + n);
    };

    ldg_q(u, 0, 0);
    ldg_q(u, 1, 1);

    while (u < kUnits) {
        const int h = u >= kTilesN ? 1 : 0;
        const int tile = u - h * kTilesN;

        if (h != cur_half) {                         // uniform branch (u is CTA-wide)
            __syncthreads();                         // all warps done reading old A
            for (int j = tid; j < kM * (kHalfK / 16); j += kThreads) {
                int row = j >> 7, sg = j & 127;      // 128 x 16B per row
                cp_async16(As_u + row * kAStride + sg * 16,
                           g_x8 + (size_t)row * kK + h * kHalfK + sg * 16);
            }
            cp_commit();
            cp_wait_all();
            __syncthreads();
            cur_half = h;
        }

        if (tid == 0) s_next[u_par] = atomicAdd(&g_counter, 1);

        int acc[4][4] = {};
#pragma unroll 2
        for (int c = 0; c < kChunks; ++c) {
            const int slot = c & 1;
            // dequant w = q*s2 + z (exact int8) -> B fragments for 4 k-steps
            const int sc = s2s[slot], zc = zzs[slot];
            uint32_t bfrag[8];
#pragma unroll
            for (int j = 0; j < 8; ++j) {
                int b0 = qv[slot][j].x * sc + zc, b1 = qv[slot][j].y * sc + zc;
                int b2 = qv[slot][j].z * sc + zc, b3 = qv[slot][j].w * sc + zc;
                uint32_t p01 = prmt((uint32_t)b0, (uint32_t)b1, 0x0040);
                uint32_t p23 = prmt((uint32_t)b2, (uint32_t)b3, 0x0040);
                bfrag[j] = prmt(p01, p23, 0x5410);
            }
            // A fragments from persistent smem, then 4 independent mma chains
            uint32_t aa[4][4];
            const uint32_t abase = As_u + a_off + c * kBK;
#pragma unroll
            for (int ks = 0; ks < 4; ++ks) ldmatrix_x4(aa[ks], abase + ks * 32);
#pragma unroll
            for (int ks = 0; ks < 4; ++ks)
                mma_s8(acc[ks], aa[ks][0], aa[ks][1], aa[ks][2], aa[ks][3],
                       bfrag[ks * 2], bfrag[ks * 2 + 1]);

            // prefetch: this unit's c+2, or next unit's c0/c1 at the tail
            if (c < kChunks - 2) {
                ldg_q(u, c + 2, slot);
            } else if (c == kChunks - 2) {
                __syncthreads();                     // publishes s_next[u_par]
                u_next = s_next[u_par];
                if (u_next < kUnits) ldg_q(u_next, 0, slot);
            } else {
                if (u_next < kUnits) ldg_q(u_next, 1, slot);
            }
        }

        // write int32 partials for this unit
        {
            const int r = mt * 16 + (lane >> 2);
            const int n = tile * kBN + nt * 8 + (lane & 3) * 2;
            int a0 = acc[0][0] + acc[1][0] + acc[2][0] + acc[3][0];
            int a1 = acc[0][1] + acc[1][1] + acc[2][1] + acc[3][1];
            int a2 = acc[0][2] + acc[1][2] + acc[2][2] + acc[3][2];
            int a3 = acc[0][3] + acc[1][3] + acc[2][3] + acc[3][3];
            *(int2*)&g_part[h][(size_t)r * kN + n] = make_int2(a0, a1);
            *(int2*)&g_part[h][(size_t)(r + 8) * kN + n] = make_int2(a2, a3);
        }

        u = u_next;
        u_par ^= 1;
    }
}

// ---------------- epilogue: sum halves, scale, bias ----------------
__global__ void epilogue_kernel(const float* __restrict__ input_scales,
                                const float* __restrict__ s1_scales,
                                const float* __restrict__ bias,
                                float* __restrict__ out) {
    int idx = blockIdx.x * blockDim.x + threadIdx.x;  // quad index over M*N/4
    int m = idx / (kN / 4);
    int n = (idx - m * (kN / 4)) * 4;
    int4 p0 = *(const int4*)&g_part[0][(size_t)m * kN + n];
    int4 p1 = *(const int4*)&g_part[1][(size_t)m * kN + n];
    float is = input_scales[m];
    float4 s = *(const float4*)(s1_scales + n);
    float4 b = *(const float4*)(bias + n);
    float4 o;
    o.x = (float)(p0.x + p1.x) * is * s.x + b.x;
    o.y = (float)(p0.y + p1.y) * is * s.y + b.y;
    o.z = (float)(p0.z + p1.z) * is * s.z + b.z;
    o.w = (float)(p0.w + p1.w) * is * s.w + b.w;
    *(float4*)(out + (size_t)m * kN + n) = o;
}

extern "C" void kernel_launch(void* const* d_in, const int* in_sizes, int n_in,
                              void* d_out, int out_size) {
    const int* x           = (const int*)d_in[0];
    const float* in_scales = (const float*)d_in[1];
    // d_in[2] = input_sum (unused)
    const int* qweight     = (const int*)d_in[3];
    const int* s2_scales   = (const int*)d_in[4];
    const int* s2_zeros    = (const int*)d_in[5];
    const float* s1_scales = (const float*)d_in[6];
    const float* bias      = (const float*)d_in[7];
    float* out             = (float*)d_out;
    (void)in_sizes; (void)n_in; (void)out_size;

    int dev = 0, nsm = 148;
    cudaGetDevice(&dev);
    cudaDeviceGetAttribute(&nsm, cudaDevAttrMultiProcessorCount, dev);

    cudaFuncSetAttribute(w4a8_gemm, cudaFuncAttributeMaxDynamicSharedMemorySize, kASmem);

    pack_x_kernel<<<64, kThreads>>>(x, nsm);
    w4a8_gemm<<<nsm, kThreads, kASmem>>>(qweight, s2_scales, s2_zeros);
    epilogue_kernel<<<kM * kN / 4 / 512, 512>>>(in_scales, s1_scales, bias, out);
}

// round 8
// speedup vs baseline: 1.7440x; 1.7440x over previous
#include <cuda_runtime.h>
#include <cstdint>
#include <cstddef>

namespace {
constexpr int kM = 64;
constexpr int kK = 4096;
constexpr int kN = 14336;
constexpr int kBN = 16;               // tile width -> grid 896
constexpr int kBK = 256;              // stage width: TWO quant groups
constexpr int kStagesK = kK / kBK;    // 16 stages
constexpr int kPad = 272;             // smem row stride (17*16B -> conflict-free)
constexpr int kAStage = 64 * kPad;    // 17408 B
constexpr int kBStage = kBN * kPad;   // 4352 B
constexpr int kThreads = 256;
}

// device-global scratch (no allocations allowed)
__device__ __align__(16) int8_t g_x8[kM * kK];  // packed int8 activations

__global__ void pack_x_kernel(const int* __restrict__ x) {
    int idx = blockIdx.x * blockDim.x + threadIdx.x;  // int4 index over M*K/4
    int4 v = __ldg(((const int4*)x) + idx);
    uint32_t w = (uint32_t)(v.x & 0xff) | ((uint32_t)(v.y & 0xff) << 8)
               | ((uint32_t)(v.z & 0xff) << 16) | ((uint32_t)(v.w & 0xff) << 24);
    ((uint32_t*)g_x8)[idx] = w;
}

// ---------------- PTX helpers ----------------
__device__ __forceinline__ uint32_t smem_u32(const void* p) {
    return (uint32_t)__cvta_generic_to_shared(p);
}
__device__ __forceinline__ void cp_async16(uint32_t dst, const void* src) {
    asm volatile("cp.async.ca.shared.global [%0], [%1], 16;\n" :: "r"(dst), "l"(src));
}
__device__ __forceinline__ void cp_commit() { asm volatile("cp.async.commit_group;\n"); }
__device__ __forceinline__ void cp_wait_all() { asm volatile("cp.async.wait_group 0;\n" ::: "memory"); }
__device__ __forceinline__ uint32_t prmt(uint32_t a, uint32_t b, uint32_t sel) {
    uint32_t d;
    asm("prmt.b32 %0, %1, %2, %3;" : "=r"(d) : "r"(a), "r"(b), "r"(sel));
    return d;
}
__device__ __forceinline__ void ldmatrix_x4(uint32_t r[4], uint32_t addr) {
    asm volatile("ldmatrix.sync.aligned.m8n8.x4.shared.b16 {%0,%1,%2,%3}, [%4];"
                 : "=r"(r[0]), "=r"(r[1]), "=r"(r[2]), "=r"(r[3]) : "r"(addr));
}
__device__ __forceinline__ void mma_s8(int c[4], uint32_t a0, uint32_t a1, uint32_t a2,
                                       uint32_t a3, uint32_t b0, uint32_t b1) {
    asm volatile(
        "mma.sync.aligned.m16n8k32.row.col.s32.s8.s8.s32 "
        "{%0,%1,%2,%3}, {%4,%5,%6,%7}, {%8,%9}, {%0,%1,%2,%3};\n"
        : "+r"(c[0]), "+r"(c[1]), "+r"(c[2]), "+r"(c[3])
        : "r"(a0), "r"(a1), "r"(a2), "r"(a3), "r"(b0), "r"(b1));
}

// ---------------- cooperative GEMM: BN=16, 256-wide stages ----------------
__global__ void __launch_bounds__(kThreads, 4)
w4a8_gemm(const int* __restrict__ qweight,
          const int* __restrict__ s2_scales,
          const int* __restrict__ s2_zeros,
          const float* __restrict__ input_scales,
          const float* __restrict__ s1_scales,
          const float* __restrict__ bias,
          float* __restrict__ out) {
    __shared__ __align__(16) int8_t As[2][kAStage];
    __shared__ __align__(16) int8_t Bs[2][kBStage];

    const int tid = threadIdx.x;
    const int warp = tid >> 5;
    const int lane = tid & 31;
    const int n0 = blockIdx.x * kBN;

    // ---- producer mapping: 16 rows x 16 segments (16 B each) over 256-wide stage
    const int nl = tid >> 4;           // 0..15 weight row in tile
    const int seg = tid & 15;          // 16B segment; seg<8 -> group 2s, else 2s+1
    const int n_glob = n0 + nl;
    const int4* qrow = (const int4*)qweight + (size_t)n_glob * (kK / 4);
    const int gsub = seg >> 3;         // which of the stage's two groups

    int4 qv[4];
    int s2r, zr;

    auto ldg_stage = [&](int s) {
#pragma unroll
        for (int j = 0; j < 4; ++j)
            qv[j] = __ldcs(qrow + s * 64 + seg * 4 + j);
        const int g = s * 2 + gsub;
        s2r = __ldg(s2_scales + (size_t)g * kN + n_glob);
        zr  = __ldg(s2_zeros + (size_t)g * kN + n_glob);
    };
    auto cp_a = [&](int s, int b) {
#pragma unroll
        for (int j = 0; j < 4; ++j) {
            int id = tid + kThreads * j;             // 0..1023
            int row = id >> 4, sg = id & 15;
            cp_async16(smem_u32(&As[b][row * kPad + sg * 16]),
                       g_x8 + (size_t)row * kK + s * kBK + sg * 16);
        }
        cp_commit();
    };
    auto dequant_sts = [&](int b) {
        // w = q*s2 + z, exact int8 (|w| <= 105); byte0 of each IMAD result
        uint32_t pk[4];
#pragma unroll
        for (int j = 0; j < 4; ++j) {
            int b0 = qv[j].x * s2r + zr, b1 = qv[j].y * s2r + zr;
            int b2 = qv[j].z * s2r + zr, b3 = qv[j].w * s2r + zr;
            uint32_t p01 = prmt((uint32_t)b0, (uint32_t)b1, 0x0040);
            uint32_t p23 = prmt((uint32_t)b2, (uint32_t)b3, 0x0040);
            pk[j] = prmt(p01, p23, 0x5410);
        }
        *(uint4*)(&Bs[b][nl * kPad + seg * 16]) = make_uint4(pk[0], pk[1], pk[2], pk[3]);
    };

    // ---- consumer mapping (validated R4/R6): warp -> (m-tile, n-tile) ----
    const int mt = warp & 3;       // 16-row m-tile
    const int nt = warp >> 2;      // 8-col n-tile
    const uint32_t a_off = (uint32_t)((mt * 16 + (lane & 7) + ((lane >> 3) & 1) * 8) * kPad
                                      + ((lane >> 4) & 1) * 16);
    const uint32_t b_off = (uint32_t)((nt * 8 + (lane & 7)) * kPad + (lane >> 3) * 16);
    int acc[2][4] = {};   // two interleaved chains

    // ---- prologue: stage 0 into buffer 0 ----
    ldg_stage(0);
    cp_a(0, 0);
    dequant_sts(0);
    cp_wait_all();
    __syncthreads();

    for (int s = 0; s < kStagesK; ++s) {
        const int b = s & 1;
        if (s + 1 < kStagesK) {
            ldg_stage(s + 1);          // long-distance issue (consumed post-mma)
            cp_a(s + 1, b ^ 1);
        }

        const uint32_t abase = smem_u32(&As[b][0]) + a_off;
        const uint32_t bbase = smem_u32(&Bs[b][0]) + b_off;
#pragma unroll
        for (int kp = 0; kp < 4; ++kp) {           // 4 x (64B of B = 2 k-steps)
            uint32_t bf[4];
            ldmatrix_x4(bf, bbase + kp * 64);
#pragma unroll
            for (int k2 = 0; k2 < 2; ++k2) {
                uint32_t a[4];
                ldmatrix_x4(a, abase + (kp * 2 + k2) * 32);
                mma_s8(acc[k2], a[0], a[1], a[2], a[3], bf[k2 * 2], bf[k2 * 2 + 1]);
            }
        }

        if (s + 1 < kStagesK) dequant_sts(b ^ 1);
        cp_wait_all();
        __syncthreads();
    }

    // ---- fused epilogue (merge the two chains) ----
    const int r = mt * 16 + (lane >> 2);
    const int n = n0 + nt * 8 + (lane & 3) * 2;
    const float is0 = input_scales[r];
    const float is1 = input_scales[r + 8];
    const float s1a = s1_scales[n], s1b = s1_scales[n + 1];
    const float ba = bias[n], bb = bias[n + 1];
    const int a0 = acc[0][0] + acc[1][0], a1 = acc[0][1] + acc[1][1];
    const int a2 = acc[0][2] + acc[1][2], a3 = acc[0][3] + acc[1][3];
    *(float2*)(out + (size_t)r * kN + n) =
        make_float2((float)a0 * is0 * s1a + ba, (float)a1 * is0 * s1b + bb);
    *(float2*)(out + (size_t)(r + 8) * kN + n) =
        make_float2((float)a2 * is1 * s1a + ba, (float)a3 * is1 * s1b + bb);
}

extern "C" void kernel_launch(void* const* d_in, const int* in_sizes, int n_in,
                              void* d_out, int out_size) {
    const int* x           = (const int*)d_in[0];
    const float* in_scales = (const float*)d_in[1];
    // d_in[2] = input_sum (unused)
    const int* qweight     = (const int*)d_in[3];
    const int* s2_scales   = (const int*)d_in[4];
    const int* s2_zeros    = (const int*)d_in[5];
    const float* s1_scales = (const float*)d_in[6];
    const float* bias      = (const float*)d_in[7];
    float* out             = (float*)d_out;
    (void)in_sizes; (void)n_in; (void)out_size;

    pack_x_kernel<<<(kM * kK / 4) / kThreads, kThreads>>>(x);
    w4a8_gemm<<<kN / kBN, kThreads>>>(qweight, s2_scales, s2_zeros,
                                      in_scales, s1_scales, bias, out);
}